// round 8
// baseline (speedup 1.0000x reference)
#include <cuda_runtime.h>
#include <cstdint>

#define NPTS 1024

// Scratch (no cudaMalloc allowed)
__device__ float    g_U [NPTS * 64];           // raw U [p][h]
__device__ float    g_Ub[NPTS * 64];           // U + b1 [p][h]
__device__ float    g_Bf[NPTS * 32];           // [p][i]
// packed B fragments: [p][i][32] u32; slot 2*(s*4+tq)+0 = b0(k2=8s+tq),
//                                     slot 2*(s*4+tq)+1 = b1(k2=8s+tq+4)
__device__ uint32_t g_Gph[NPTS * 32 * 32];
__device__ uint32_t g_Gpm[NPTS * 32 * 32];

// ===========================================================================
// helpers
// ===========================================================================
__device__ __forceinline__ uint32_t bf16x2_of(float lo, float hi) {
    uint32_t r;
    asm("cvt.rn.bf16x2.f32 %0, %1, %2;" : "=r"(r) : "f"(hi), "f"(lo));
    return r;
}
__device__ __forceinline__ float bf_lo(uint32_t p) { return __uint_as_float(p << 16); }
__device__ __forceinline__ float bf_hi(uint32_t p) { return __uint_as_float(p & 0xFFFF0000u); }

__device__ __forceinline__ void split_u64(unsigned long long v, uint32_t& ph, uint32_t& pm) {
    float lo = __uint_as_float((uint32_t)v);
    float hi = __uint_as_float((uint32_t)(v >> 32));
    ph = bf16x2_of(lo, hi);
    pm = bf16x2_of(lo - bf_lo(ph), hi - bf_hi(ph));
}

__device__ __forceinline__ void mma_bf16(float* c, uint32_t a0, uint32_t a1,
                                         uint32_t a2, uint32_t a3,
                                         uint32_t b0, uint32_t b1) {
    asm("mma.sync.aligned.m16n8k16.row.col.f32.bf16.bf16.f32 "
        "{%0,%1,%2,%3},{%4,%5,%6,%7},{%8,%9},{%0,%1,%2,%3};"
        : "+f"(c[0]), "+f"(c[1]), "+f"(c[2]), "+f"(c[3])
        : "r"(a0), "r"(a1), "r"(a2), "r"(a3), "r"(b0), "r"(b1));
}

// ===========================================================================
// Fused precompute (grid 32x8, 256 thr): U/Ub/Bf (4 pts/blk) + G SGEMM
//   G[p][i][h] = sum_j W2[h][i*32+j] * feat[p][j]  -> packed bf16 hi/mid frags
// ===========================================================================
#define FS_PAD 33
__global__ void __launch_bounds__(256) pre_all(
    const float* __restrict__ geo, const float* __restrict__ feat,
    const float* __restrict__ W1, const float* __restrict__ b1,
    const float* __restrict__ W2, const float* __restrict__ b2) {
    int bx = blockIdx.x, by = blockIdx.y;
    int t = threadIdx.x;

    {   // U, Ub, Bf for 4 points
        int pb = (by * 32 + bx) * 4;
        {
            int pl = t >> 6, h = t & 63;
            int p = pb + pl;
            float gx = geo[p * 3], gy = geo[p * 3 + 1], gz = geo[p * 3 + 2];
            float u = gx * W1[h] + gy * W1[64 + h] + gz * W1[128 + h];
            g_U[p * 64 + h] = u;
            g_Ub[p * 64 + h] = u + b1[h];
        }
        if (t < 128) {
            int pl = t >> 5, i = t & 31;
            const float4* bw = (const float4*)(b2 + i * 32);
            const float4* fv = (const float4*)(feat + (size_t)(pb + pl) * 32);
            float s = 0.f;
            #pragma unroll
            for (int j = 0; j < 8; ++j) {
                float4 w = bw[j], f = fv[j];
                s += w.x * f.x + w.y * f.y + w.z * f.z + w.w * f.w;
            }
            g_Bf[(pb + pl) * 32 + i] = s;
        }
    }

    // G SGEMM, block tile 32p x 256e, e = i_l*64 + h
    int pbase = bx * 32;
    int i0g = by * 4;
    int pg = t & 7, eg = t >> 3;
    int p0 = pg * 4, e0 = eg * 8;

    __shared__ float Fs[32 * FS_PAD];
    __shared__ float Ws[32][264];

    #pragma unroll
    for (int k = 0; k < 4; ++k) {
        int idx = t + k * 256;
        int p = idx >> 5, j = idx & 31;
        Fs[p * FS_PAD + j] = feat[(size_t)(pbase + p) * 32 + j];
    }
    {
        int lane = t & 31, w = t >> 5;
        int j4 = lane & 7, sub = lane >> 3;
        #pragma unroll
        for (int q = 0; q < 8; ++q) {
            int pidx = w * 32 + q * 4 + sub;
            int il = pidx >> 6, h = pidx & 63;
            float4 v = ((const float4*)W2)[((size_t)h * 1024 + (i0g + il) * 32) / 4 + j4];
            int e = il * 64 + h;
            Ws[j4 * 4 + 0][e] = v.x;
            Ws[j4 * 4 + 1][e] = v.y;
            Ws[j4 * 4 + 2][e] = v.z;
            Ws[j4 * 4 + 3][e] = v.w;
        }
    }
    __syncthreads();

    ulonglong2 acc[4][2];
    #pragma unroll
    for (int r = 0; r < 4; ++r) {
        acc[r][0].x = acc[r][0].y = 0ull;
        acc[r][1].x = acc[r][1].y = 0ull;
    }
    #pragma unroll 8
    for (int j = 0; j < 32; ++j) {
        ulonglong2 w0 = *(const ulonglong2*)&Ws[j][e0];
        ulonglong2 w1 = *(const ulonglong2*)&Ws[j][e0 + 4];
        #pragma unroll
        for (int r = 0; r < 4; ++r) {
            float f = Fs[(p0 + r) * FS_PAD + j];
            unsigned long long s;
            unsigned int fb = __float_as_uint(f);
            asm("mov.b64 %0, {%1, %1};" : "=l"(s) : "r"(fb));
            asm("fma.rn.f32x2 %0, %1, %2, %0;" : "+l"(acc[r][0].x) : "l"(s), "l"(w0.x));
            asm("fma.rn.f32x2 %0, %1, %2, %0;" : "+l"(acc[r][0].y) : "l"(s), "l"(w0.y));
            asm("fma.rn.f32x2 %0, %1, %2, %0;" : "+l"(acc[r][1].x) : "l"(s), "l"(w1.x));
            asm("fma.rn.f32x2 %0, %1, %2, %0;" : "+l"(acc[r][1].y) : "l"(s), "l"(w1.y));
        }
    }

    // epilogue: bf16 hi/mid split, scatter into packed-fragment slots
    int il = e0 >> 6, i = i0g + il;
    int k2b = (e0 & 63) >> 1;                 // 4 consecutive k2, same 8-block
    int half = (k2b >> 2) & 1;
    int sb4 = (k2b >> 3) * 4;                 // entry base q
    #pragma unroll
    for (int r = 0; r < 4; ++r) {
        int p = pbase + p0 + r;
        uint4 vh, vm;
        split_u64(acc[r][0].x, vh.x, vm.x);
        split_u64(acc[r][0].y, vh.y, vm.y);
        split_u64(acc[r][1].x, vh.z, vm.z);
        split_u64(acc[r][1].y, vh.w, vm.w);
        uint32_t* dh = g_Gph + ((size_t)p * 32 + i) * 32;
        uint32_t* dm = g_Gpm + ((size_t)p * 32 + i) * 32;
        dh[(sb4 + 0) * 2 + half] = vh.x;  dm[(sb4 + 0) * 2 + half] = vm.x;
        dh[(sb4 + 1) * 2 + half] = vh.y;  dm[(sb4 + 1) * 2 + half] = vm.y;
        dh[(sb4 + 2) * 2 + half] = vh.z;  dm[(sb4 + 2) * 2 + half] = vm.z;
        dh[(sb4 + 3) * 2 + half] = vh.w;  dm[(sb4 + 3) * 2 + half] = vm.w;
    }
}

// ===========================================================================
// Pair kernel: bf16 3-product MMA, 2 points/block, 512 blocks, 256 thr.
// U smem in [a][h] layout (pitch 72) -> LDS.64 A loads, conflict-free.
// B pre-packed uint2 frags (pitch 40 u32) -> LDS.64 B loads, conflict-free.
// ===========================================================================
#define U_P 72
#define G_P32 40
#define ST_P 36
#define O_US  0
#define O_G0H 18432
#define O_G0M (O_G0H + 1280)
#define O_G1H (O_G0M + 1280)
#define O_G1M (O_G1H + 1280)
#define O_UB0 (O_G1M + 1280)
#define O_UB1 (O_UB0 + 64)
#define O_BF0 (O_UB1 + 64)
#define O_BF1 (O_BF0 + 32)
#define SMF   (O_BF1 + 32)      // 23744 floats = 94976 B

__global__ void __launch_bounds__(256, 2) pair_kernel(float* __restrict__ out) {
    extern __shared__ float sm[];
    int p0 = blockIdx.x * 2;
    int z = p0 >> 8, b0 = p0 & 255;
    int t = threadIdx.x, lane = t & 31, wid = t >> 5;
    int g = lane >> 2, tq = lane & 3;

    // ---- fills ----
    #pragma unroll
    for (int it = 0; it < 16; ++it) {          // Us: 256 rows x 16 float4
        int idx = it * 256 + t;
        int a = idx >> 4, h4 = idx & 15;
        float4 v = ((const float4*)g_U)[(size_t)(z * 256 + a) * 16 + h4];
        *(float4*)(sm + O_US + a * U_P + h4 * 4) = v;
    }
    {   // G: 4 arrays, 1 uint4 per thread each (pitch remap 32 -> 40 u32)
        int i = t >> 3, c4 = (t & 7) * 4;
        size_t s0 = ((size_t)p0 * 32 + i) * 32 + c4;
        size_t s1 = ((size_t)(p0 + 1) * 32 + i) * 32 + c4;
        int d = i * G_P32 + c4;
        *(uint4*)((uint32_t*)(sm + O_G0H) + d) = *(const uint4*)(g_Gph + s0);
        *(uint4*)((uint32_t*)(sm + O_G0M) + d) = *(const uint4*)(g_Gpm + s0);
        *(uint4*)((uint32_t*)(sm + O_G1H) + d) = *(const uint4*)(g_Gph + s1);
        *(uint4*)((uint32_t*)(sm + O_G1M) + d) = *(const uint4*)(g_Gpm + s1);
    }
    if (t < 64) sm[O_UB0 + t] = g_Ub[p0 * 64 + t];
    else if (t < 128) sm[O_UB1 + t - 64] = g_Ub[(p0 + 1) * 64 + (t - 64)];
    else if (t < 160) sm[O_BF0 + t - 128] = g_Bf[p0 * 32 + (t - 128)];
    else if (t < 192) sm[O_BF1 + t - 160] = g_Bf[(p0 + 1) * 32 + (t - 160)];
    __syncthreads();

    float acc[2][2][4][4];
    #pragma unroll
    for (int pt = 0; pt < 2; ++pt)
        #pragma unroll
        for (int mi = 0; mi < 2; ++mi)
            #pragma unroll
            for (int n = 0; n < 4; ++n)
                acc[pt][mi][n][0] = acc[pt][mi][n][1] =
                acc[pt][mi][n][2] = acc[pt][mi][n][3] = 0.f;

    // ---- mainloop: 4 k16 steps ----
    #pragma unroll
    for (int s = 0; s < 4; ++s) {
        int kb = 16 * s;
        // A-side raw U: float2 loads, conflict-free (pitch 72)
        float2 u01[2][4];
        #pragma unroll
        for (int mi = 0; mi < 2; ++mi) {
            #pragma unroll
            for (int j = 0; j < 4; ++j) {
                int row = wid * 32 + mi * 16 + g + (j & 1) * 8;
                int col = kb + 2 * tq + (j >> 1) * 8;
                u01[mi][j] = *(const float2*)(sm + O_US + row * U_P + col);
            }
        }
        #pragma unroll
        for (int pt = 0; pt < 2; ++pt) {
            const float* ub = sm + (pt ? O_UB1 : O_UB0);
            float2 ubL = *(const float2*)(ub + kb + 2 * tq);
            float2 ubH = *(const float2*)(ub + kb + 2 * tq + 8);
            uint32_t Ah[2][4], Am[2][4];
            #pragma unroll
            for (int mi = 0; mi < 2; ++mi) {
                #pragma unroll
                for (int j = 0; j < 4; ++j) {
                    float2 e = (j >> 1) ? ubH : ubL;
                    float h0 = fmaxf(e.x - u01[mi][j].x, 0.f);
                    float h1 = fmaxf(e.y - u01[mi][j].y, 0.f);
                    uint32_t ph = bf16x2_of(h0, h1);
                    Ah[mi][j] = ph;
                    Am[mi][j] = bf16x2_of(h0 - bf_lo(ph), h1 - bf_hi(ph));
                }
            }
            const uint32_t* Gh = (const uint32_t*)(sm + (pt ? O_G1H : O_G0H));
            const uint32_t* Gm = (const uint32_t*)(sm + (pt ? O_G1M : O_G0M));
            #pragma unroll
            for (int n = 0; n < 4; ++n) {
                int bi = (n * 8 + g) * G_P32 + (s * 4 + tq) * 2;
                uint2 bh = *(const uint2*)(Gh + bi);
                uint2 bm = *(const uint2*)(Gm + bi);
                #pragma unroll
                for (int mi = 0; mi < 2; ++mi) {
                    mma_bf16(acc[pt][mi][n], Ah[mi][0], Ah[mi][1], Ah[mi][2], Ah[mi][3], bh.x, bh.y);
                    mma_bf16(acc[pt][mi][n], Ah[mi][0], Ah[mi][1], Ah[mi][2], Ah[mi][3], bm.x, bm.y);
                    mma_bf16(acc[pt][mi][n], Am[mi][0], Am[mi][1], Am[mi][2], Am[mi][3], bh.x, bh.y);
                }
            }
        }
    }
    __syncthreads();   // Us dead -> reuse as stage

    // ---- epilogue per point: stage -> +Bf -> coalesced STG.128 ----
    float* st = sm + O_US;
    #pragma unroll
    for (int pt = 0; pt < 2; ++pt) {
        #pragma unroll
        for (int mi = 0; mi < 2; ++mi) {
            int row = wid * 32 + mi * 16 + g;
            #pragma unroll
            for (int n = 0; n < 4; ++n) {
                int col = n * 8 + 2 * tq;
                float2 v0 = {acc[pt][mi][n][0], acc[pt][mi][n][1]};
                float2 v1 = {acc[pt][mi][n][2], acc[pt][mi][n][3]};
                *(float2*)(st + row * ST_P + col) = v0;
                *(float2*)(st + (row + 8) * ST_P + col) = v1;
            }
        }
        __syncthreads();
        const float* bfp = sm + (pt ? O_BF1 : O_BF0);
        int b = b0 + pt;
        #pragma unroll
        for (int it = 0; it < 8; ++it) {
            int idx = it * 256 + t;
            int row = idx >> 3, c4 = idx & 7;
            float4 v = *(const float4*)(st + row * ST_P + c4 * 4);
            float4 bf = *(const float4*)(bfp + c4 * 4);
            v.x += bf.x; v.y += bf.y; v.z += bf.z; v.w += bf.w;
            *(float4*)(out + (((size_t)(z * 256 + row)) * 256 + b) * 32 + c4 * 4) = v;
        }
        __syncthreads();
    }
}

// ===========================================================================
extern "C" void kernel_launch(void* const* d_in, const int* in_sizes, int n_in,
                              void* d_out, int out_size) {
    const float* feat = (const float*)d_in[0];
    const float* geo  = (const float*)d_in[1];
    const float* W1   = (const float*)d_in[2];
    const float* b1   = (const float*)d_in[3];
    const float* W2   = (const float*)d_in[4];
    const float* b2   = (const float*)d_in[5];
    float* out = (float*)d_out;

    cudaFuncSetAttribute(pair_kernel, cudaFuncAttributeMaxDynamicSharedMemorySize,
                         SMF * 4);

    pre_all<<<dim3(32, 8), 256>>>(geo, feat, W1, b1, W2, b2);
    pair_kernel<<<512, 256, SMF * 4>>>(out);
}